// round 15
// baseline (speedup 1.0000x reference)
#include <cuda_runtime.h>
#include <cuda_bf16.h>
#include <math.h>

#define B_ 4
#define T_ 1024
#define D_ 1024
#define H_ 16
#define K_ 64
#define BT_ (B_*T_)        // 4096
#define BTD (BT_*D_)       // 4194304
#define DD_ (D_*D_)

// ---------------- scratch (static device globals; no runtime alloc) --------
__device__ float g_dx[BTD];
__device__ float g_xmix[BTD];
__device__ float g_xxx[BT_*160];
__device__ float g_xw[BTD];             // fp32 xw for decay chain
__device__ float g_r[BTD], g_k[BTD], g_v[BTD], g_gt[BTD], g_w[BTD];
__device__ float g_wtmp[BT_*64];
__device__ float g_yh[BTD];
__device__ float g_pfx[64*64*64];       // [bh][subchunk16][kx] exclusive prefix
__device__ float g_shfA[64*64], g_shbA[64*64];

__device__ __nv_bfloat16 g_xmh[4*BTD], g_xml[4*BTD];   // k,v,r,g mixes (split)
__device__ __nv_bfloat16 g_Wh[5*DD_],  g_Wl[5*DD_];    // W_r,W_k,W_v,W_g,W_o
__device__ __nv_bfloat16 g_rfh[BTD], g_rfl[BTD];
__device__ __nv_bfloat16 g_kfh[BTD], g_kfl[BTD];
__device__ __nv_bfloat16 g_rbh[BTD], g_rbl[BTD];
__device__ __nv_bfloat16 g_kbh[BTD], g_kbl[BTD];
__device__ __nv_bfloat16 g_vhh[BTD], g_vll[BTD];
__device__ __nv_bfloat16 g_ygh[BTD], g_ygl[BTD];

enum { EP_NONE=0, EP_TANH=1, EP_SILU=2, EP_BIAS=3 };

// ---------------- helpers ----------------------------------------------------
__device__ __forceinline__ unsigned tf32_of(float x) {
    unsigned u; asm("cvt.rna.tf32.f32 %0, %1;" : "=r"(u) : "f"(x)); return u;
}
__device__ __forceinline__ float tf32f(float x) {
    return __uint_as_float(tf32_of(x));
}
__device__ __forceinline__ void mma_tf32(float c[4], unsigned a0, unsigned a1,
                                         unsigned a2, unsigned a3,
                                         unsigned b0, unsigned b1) {
    asm volatile(
        "mma.sync.aligned.m16n8k8.row.col.f32.tf32.tf32.f32 "
        "{%0,%1,%2,%3},{%4,%5,%6,%7},{%8,%9},{%0,%1,%2,%3};"
        : "+f"(c[0]), "+f"(c[1]), "+f"(c[2]), "+f"(c[3])
        : "r"(a0), "r"(a1), "r"(a2), "r"(a3), "r"(b0), "r"(b1));
}
__device__ __forceinline__ void mma_bf16(float c[4], unsigned a0, unsigned a1,
                                         unsigned a2, unsigned a3,
                                         unsigned b0, unsigned b1) {
    asm volatile(
        "mma.sync.aligned.m16n8k16.row.col.f32.bf16.bf16.f32 "
        "{%0,%1,%2,%3},{%4,%5,%6,%7},{%8,%9},{%0,%1,%2,%3};"
        : "+f"(c[0]), "+f"(c[1]), "+f"(c[2]), "+f"(c[3])
        : "r"(a0), "r"(a1), "r"(a2), "r"(a3), "r"(b0), "r"(b1));
}
__device__ __forceinline__ void bsplit(float x, __nv_bfloat16& h, __nv_bfloat16& l) {
    h = __float2bfloat16(x);
    l = __float2bfloat16(x - __bfloat162float(h));
}
__device__ __forceinline__ unsigned sm_addr(const void* p) {
    return (unsigned)__cvta_generic_to_shared(p);
}
__device__ __forceinline__ void ldsm4(unsigned& r0, unsigned& r1,
                                      unsigned& r2, unsigned& r3, unsigned a) {
    asm volatile("ldmatrix.sync.aligned.m8n8.x4.shared.b16 {%0,%1,%2,%3}, [%4];"
        : "=r"(r0), "=r"(r1), "=r"(r2), "=r"(r3) : "r"(a));
}
__device__ __forceinline__ void ldsm4t(unsigned& r0, unsigned& r1,
                                       unsigned& r2, unsigned& r3, unsigned a) {
    asm volatile("ldmatrix.sync.aligned.m8n8.x4.trans.shared.b16 {%0,%1,%2,%3}, [%4];"
        : "=r"(r0), "=r"(r1), "=r"(r2), "=r"(r3) : "r"(a));
}
#define CP16(dst, src) asm volatile( \
    "cp.async.cg.shared.global [%0], [%1], 16;" :: "r"(dst), "l"(src))
#define CP_COMMIT() asm volatile("cp.async.commit_group;")

// ---------------- prep: dxprev + xmix ---------------------------------------
__global__ void prep_kernel(const float* __restrict__ x,
                            const float* __restrict__ maa_x) {
    int idx = blockIdx.x*256 + threadIdx.x;
    if (idx >= BTD) return;
    int d = idx & (D_-1);
    int t = (idx >> 10) & (T_-1);
    float xc = x[idx];
    float left  = (t > 0)     ? x[idx - D_] : 0.f;
    float right = (t < T_-1)  ? x[idx + D_] : 0.f;
    float dx = 0.5f*(left + right) - xc;
    g_dx[idx]   = dx;
    g_xmix[idx] = xc + dx * maa_x[d];
}

// ---------------- split all 5 weights into bf16 hi/lo (vectorized) ----------
__global__ void split5_kernel(const float* __restrict__ w0,
                              const float* __restrict__ w1,
                              const float* __restrict__ w2,
                              const float* __restrict__ w3,
                              const float* __restrict__ w4) {
    const float* srcs[5] = {w0, w1, w2, w3, w4};
    size_t q = (size_t)blockIdx.x*256 + threadIdx.x;   // float4 index
    const size_t QW = DD_/4;
    if (q >= 5*QW) return;
    int wi = (int)(q / QW);
    size_t r = q - (size_t)wi*QW;
    float4 v = ((const float4*)srcs[wi])[r];
    __nv_bfloat16 h0,l0,h1,l1,h2,l2,h3,l3;
    bsplit(v.x,h0,l0); bsplit(v.y,h1,l1); bsplit(v.z,h2,l2); bsplit(v.w,h3,l3);
    __nv_bfloat162* Hp = (__nv_bfloat162*)(g_Wh + (size_t)wi*DD_ + r*4);
    __nv_bfloat162* Lp = (__nv_bfloat162*)(g_Wl + (size_t)wi*DD_ + r*4);
    Hp[0] = __halves2bfloat162(h0,h1); Hp[1] = __halves2bfloat162(h2,h3);
    Lp[0] = __halves2bfloat162(l0,l1); Lp[1] = __halves2bfloat162(l2,l3);
}

// ---------------- tf32 tensor-core GEMM (NN), with TANH/BIAS epilogues ------
template<int EP>
__global__ __launch_bounds__(256)
void mma_gemm(const float* __restrict__ A, int lda,
              const float* __restrict__ Bm, int ldb,
              float* __restrict__ C, int ldc,
              int M, int N, int Kd,
              const float* __restrict__ bias)
{
    __shared__ float As[128][20];
    __shared__ float Bs[64][20];
    const int tid  = threadIdx.x;
    const int lane = tid & 31, w = tid >> 5;
    const int g = lane >> 2, t4 = lane & 3;
    const int m0 = blockIdx.y * 128, n0 = blockIdx.x * 64;
    const int mw = w * 16;

    float acc[8][4];
    #pragma unroll
    for (int i=0;i<8;i++)
        #pragma unroll
        for (int j=0;j<4;j++) acc[i][j]=0.f;

    for (int k0 = 0; k0 < Kd; k0 += 16) {
        {
            int r = tid >> 1, c = (tid & 1) * 8;
            const float* ap = A + (size_t)(m0 + r) * lda + k0 + c;
            float4 v0 = *(const float4*)(ap);
            float4 v1 = *(const float4*)(ap + 4);
            As[r][c+0]=tf32f(v0.x); As[r][c+1]=tf32f(v0.y);
            As[r][c+2]=tf32f(v0.z); As[r][c+3]=tf32f(v0.w);
            As[r][c+4]=tf32f(v1.x); As[r][c+5]=tf32f(v1.y);
            As[r][c+6]=tf32f(v1.z); As[r][c+7]=tf32f(v1.w);
        }
        {
            int n = tid & 63, kk = tid >> 6;
            int gn = n0 + n;
            #pragma unroll
            for (int q=0;q<4;q++) {
                int gk = k0 + kk + q*4;
                float v = (gn < N) ? Bm[(size_t)gk*ldb + gn] : 0.f;
                Bs[n][kk + q*4] = tf32f(v);
            }
        }
        __syncthreads();
        #pragma unroll
        for (int kc=0; kc<16; kc+=8) {
            unsigned a0 = __float_as_uint(As[mw+g  ][kc+t4  ]);
            unsigned a1 = __float_as_uint(As[mw+g+8][kc+t4  ]);
            unsigned a2 = __float_as_uint(As[mw+g  ][kc+t4+4]);
            unsigned a3 = __float_as_uint(As[mw+g+8][kc+t4+4]);
            #pragma unroll
            for (int nt=0; nt<8; nt++) {
                unsigned b0 = __float_as_uint(Bs[nt*8+g][kc+t4  ]);
                unsigned b1 = __float_as_uint(Bs[nt*8+g][kc+t4+4]);
                mma_tf32(acc[nt], a0,a1,a2,a3, b0,b1);
            }
        }
        __syncthreads();
    }
    #pragma unroll
    for (int nt=0; nt<8; nt++) {
        #pragma unroll
        for (int e=0; e<4; e++) {
            int m = m0 + mw + g + ((e>=2)?8:0);
            int n = n0 + nt*8 + 2*t4 + (e&1);
            if (n >= N) continue;
            float v = acc[nt][e];
            if (EP == EP_TANH)      v = tanhf(v);
            else if (EP == EP_BIAS) v = v + bias[n];
            C[(size_t)m*ldc + n] = v;
        }
    }
}

// ---------------- batched bf16x3 GEMM, NT, 128x128, 2-stage cp.async+ldsm ---
struct GemmJob {
    const __nv_bfloat16 *Ah, *Al, *Bh, *Bl;
    float* C;
    int silu;
};
struct GemmBatch { GemmJob j[4]; };

__global__ __launch_bounds__(256)
void bgemm2(GemmBatch batch)
{
    __shared__ __nv_bfloat16 sA[2][2][128][24];   // [buf][h/l][m][k]
    __shared__ __nv_bfloat16 sB[2][2][128][24];   // [buf][h/l][n][k]
    const GemmJob job = batch.j[blockIdx.z];
    const int tid = threadIdx.x, lane = tid & 31, w = tid >> 5;
    const int g = lane >> 2, t4 = lane & 3;
    const int m0 = blockIdx.y * 128, n0 = blockIdx.x * 128;
    const int wm = (w & 3) * 32, wn = (w >> 2) * 64;
    const int ra = (lane & 7) + ((lane >> 3) & 1) * 8;
    const int ca = ((lane >> 4) & 1) * 8;
    const int rb = (lane & 7) + ((lane >> 4) & 1) * 8;
    const int cb = ((lane >> 3) & 1) * 8;

    float acc[2][8][4];
    #pragma unroll
    for (int a=0;a<2;a++)
        #pragma unroll
        for (int i=0;i<8;i++)
            #pragma unroll
            for (int j=0;j<4;j++) acc[a][i][j]=0.f;

    const int r = tid >> 1, c0 = (tid & 1) * 8;
    const __nv_bfloat16* srcAh = job.Ah + (size_t)(m0 + r)*D_ + c0;
    const __nv_bfloat16* srcAl = job.Al + (size_t)(m0 + r)*D_ + c0;
    const __nv_bfloat16* srcBh = job.Bh + (size_t)(n0 + r)*D_ + c0;
    const __nv_bfloat16* srcBl = job.Bl + (size_t)(n0 + r)*D_ + c0;

    auto issue = [&](int s, int buf) {
        int k0 = s * 16;
        CP16(sm_addr(&sA[buf][0][r][c0]), srcAh + k0);
        CP16(sm_addr(&sA[buf][1][r][c0]), srcAl + k0);
        CP16(sm_addr(&sB[buf][0][r][c0]), srcBh + k0);
        CP16(sm_addr(&sB[buf][1][r][c0]), srcBl + k0);
        CP_COMMIT();
    };
    issue(0, 0);

    int buf = 0;
    for (int s = 0; s < 64; s++) {
        if (s + 1 < 64) {
            issue(s + 1, buf ^ 1);
            asm volatile("cp.async.wait_group 1;");
        } else {
            asm volatile("cp.async.wait_group 0;");
        }
        __syncthreads();

        unsigned ah[2][4], al[2][4];
        #pragma unroll
        for (int ms=0; ms<2; ms++) {
            ldsm4(ah[ms][0], ah[ms][1], ah[ms][2], ah[ms][3],
                  sm_addr(&sA[buf][0][wm + ms*16 + ra][ca]));
            ldsm4(al[ms][0], al[ms][1], al[ms][2], al[ms][3],
                  sm_addr(&sA[buf][1][wm + ms*16 + ra][ca]));
        }
        #pragma unroll
        for (int ntp=0; ntp<4; ntp++) {
            unsigned bh0,bh1,bh2,bh3, bl0,bl1,bl2,bl3;
            ldsm4(bh0,bh1,bh2,bh3, sm_addr(&sB[buf][0][wn + ntp*16 + rb][cb]));
            ldsm4(bl0,bl1,bl2,bl3, sm_addr(&sB[buf][1][wn + ntp*16 + rb][cb]));
            #pragma unroll
            for (int ms=0; ms<2; ms++) {
                mma_bf16(acc[ms][ntp*2  ], ah[ms][0],ah[ms][1],ah[ms][2],ah[ms][3], bh0,bh1);
                mma_bf16(acc[ms][ntp*2  ], al[ms][0],al[ms][1],al[ms][2],al[ms][3], bh0,bh1);
                mma_bf16(acc[ms][ntp*2  ], ah[ms][0],ah[ms][1],ah[ms][2],ah[ms][3], bl0,bl1);
                mma_bf16(acc[ms][ntp*2+1], ah[ms][0],ah[ms][1],ah[ms][2],ah[ms][3], bh2,bh3);
                mma_bf16(acc[ms][ntp*2+1], al[ms][0],al[ms][1],al[ms][2],al[ms][3], bh2,bh3);
                mma_bf16(acc[ms][ntp*2+1], ah[ms][0],ah[ms][1],ah[ms][2],ah[ms][3], bl2,bl3);
            }
        }
        __syncthreads();
        buf ^= 1;
    }

    #pragma unroll
    for (int ms=0; ms<2; ms++)
        #pragma unroll
        for (int nt=0; nt<8; nt++)
            #pragma unroll
            for (int pr=0; pr<2; pr++) {
                int mm = m0 + wm + ms*16 + g + pr*8;
                int nn = n0 + wn + nt*8 + 2*t4;
                float v0 = acc[ms][nt][pr*2], v1 = acc[ms][nt][pr*2+1];
                if (job.silu) {
                    v0 = v0 / (1.f + expf(-v0));
                    v1 = v1 / (1.f + expf(-v1));
                }
                float2 vv = make_float2(v0, v1);
                *(float2*)&job.C[(size_t)mm*D_ + nn] = vv;
            }
}

// ---------------- mix (one f per blockIdx.z): x + dx*(maa_f + xxx_f@w2_f) ---
__global__ __launch_bounds__(256)
void mix_fused2(const float* __restrict__ x,
                const float* __restrict__ w2,      // (5,32,1024)
                const float* __restrict__ mw_, const float* __restrict__ mk_,
                const float* __restrict__ mv_, const float* __restrict__ mr_,
                const float* __restrict__ mg_)
{
    __shared__ float As[128][36];
    __shared__ float Bs[32][68];
    const int tid = threadIdx.x, lane = tid & 31, w = tid >> 5;
    const int g = lane >> 2, t4 = lane & 3;
    const int m0 = blockIdx.y * 128, n0 = blockIdx.x * 64;
    const int f  = blockIdx.z;
    const int mw2 = w * 16;
    const float* maas[5] = {mw_, mk_, mv_, mr_, mg_};
    const float* maa = maas[f];

    {
        int r = tid >> 1, c0 = (tid & 1) * 16;
        const float* ap = g_xxx + (size_t)(m0 + r) * 160 + f*32 + c0;
        #pragma unroll
        for (int q=0;q<4;q++) {
            float4 v = *(const float4*)(ap + q*4);
            As[r][c0+q*4+0]=tf32f(v.x); As[r][c0+q*4+1]=tf32f(v.y);
            As[r][c0+q*4+2]=tf32f(v.z); As[r][c0+q*4+3]=tf32f(v.w);
        }
    }
    {
        int kk = tid >> 3, c0 = (tid & 7) * 8;
        const float* bp = w2 + (size_t)f*32*D_ + (size_t)kk*D_ + n0 + c0;
        #pragma unroll
        for (int q=0;q<2;q++) {
            float4 v = *(const float4*)(bp + q*4);
            Bs[kk][c0+q*4+0]=tf32f(v.x); Bs[kk][c0+q*4+1]=tf32f(v.y);
            Bs[kk][c0+q*4+2]=tf32f(v.z); Bs[kk][c0+q*4+3]=tf32f(v.w);
        }
    }
    __syncthreads();

    float acc[8][4];
    #pragma unroll
    for (int i=0;i<8;i++)
        #pragma unroll
        for (int j=0;j<4;j++) acc[i][j]=0.f;
    #pragma unroll
    for (int kc=0; kc<32; kc+=8) {
        unsigned a0 = __float_as_uint(As[mw2+g  ][kc+t4  ]);
        unsigned a1 = __float_as_uint(As[mw2+g+8][kc+t4  ]);
        unsigned a2 = __float_as_uint(As[mw2+g  ][kc+t4+4]);
        unsigned a3 = __float_as_uint(As[mw2+g+8][kc+t4+4]);
        #pragma unroll
        for (int nt=0; nt<8; nt++) {
            unsigned b0 = __float_as_uint(Bs[kc+t4  ][nt*8+g]);
            unsigned b1 = __float_as_uint(Bs[kc+t4+4][nt*8+g]);
            mma_tf32(acc[nt], a0,a1,a2,a3, b0,b1);
        }
    }
    #pragma unroll
    for (int nt=0; nt<8; nt++) {
        #pragma unroll
        for (int pr=0; pr<2; pr++) {
            int ml = mw2 + g + pr*8;
            int nl = nt*8 + 2*t4;
            size_t idx = (size_t)(m0+ml)*D_ + n0 + nl;
            float2 xv  = *(const float2*)&x[idx];
            float2 dxv = *(const float2*)&g_dx[idx];
            float v0 = acc[nt][pr*2],   v1 = acc[nt][pr*2+1];
            float r0 = xv.x + dxv.x*(maa[n0+nl]   + v0);
            float r1 = xv.y + dxv.y*(maa[n0+nl+1] + v1);
            if (f == 0) {
                *(float2*)&g_xw[idx] = make_float2(r0, r1);
            } else {
                __nv_bfloat16 h0,l0,h1,l1;
                bsplit(r0,h0,l0); bsplit(r1,h1,l1);
                *(__nv_bfloat162*)&g_xmh[(size_t)(f-1)*BTD + idx] = __halves2bfloat162(h0,h1);
                *(__nv_bfloat162*)&g_xml[(size_t)(f-1)*BTD + idx] = __halves2bfloat162(l0,l1);
            }
        }
    }
}

// ---------------- headprep pass 1: 16-step-granular prefix sums -------------
__global__ __launch_bounds__(1024)
void headprep_sums() {
    int bh = blockIdx.x;
    int b = bh >> 4, h = bh & 15;
    int tid = threadIdx.x;
    int c = tid >> 6, kx = tid & 63;     // c: 0..15 (64-step chunk)
    __shared__ float sub[64][64];        // [subchunk16][kx]
    __shared__ float w512[64];
    const size_t ibase = (size_t)b*T_*D_ + (size_t)h*K_ + kx;
    #pragma unroll
    for (int q=0; q<4; q++) {
        float s = 0.f;
        #pragma unroll 4
        for (int i=0; i<16; i++) {
            int t = c*64 + q*16 + i;
            float wv = -expf(g_w[ibase + (size_t)t*D_]);
            if (t == 512) w512[kx] = wv;
            s += wv;
        }
        sub[c*4+q][kx] = s;
    }
    __syncthreads();
    if (tid < 64) {
        float run = 0.f, shb = 0.f;
        #pragma unroll
        for (int sc=0; sc<64; sc++) {
            if (sc == 32) shb = run;
            g_pfx[((size_t)bh*64 + sc)*64 + tid] = run;
            run += sub[sc][tid];
        }
        g_shbA[bh*64 + tid] = shb;
        g_shfA[bh*64 + tid] = shb + w512[tid];
    }
}

// ---------------- headprep pass 2: exp factors, full-chip parallel ----------
__global__ __launch_bounds__(256)
void headprep2() {
    int bh = blockIdx.x, blkc = blockIdx.y;        // blkc: 0..15
    int b = bh >> 4, h = bh & 15;
    int tid = threadIdx.x;
    int q = tid >> 6, kx = tid & 63;               // q: 0..3
    int sc = blkc*4 + q;
    int t0 = sc*16;
    const size_t ibase = (size_t)b*T_*D_ + (size_t)h*K_ + kx;
    float cs = g_pfx[((size_t)bh*64 + sc)*64 + kx];
    float sf = g_shfA[bh*64 + kx], sb = g_shbA[bh*64 + kx];
    size_t obase = (size_t)bh*T_*K_ + kx;
    #pragma unroll 4
    for (int i=0; i<16; i++) {
        int t = t0 + i;
        size_t gi = ibase + (size_t)t*D_;
        float wv = -expf(g_w[gi]);
        float cprev = cs;
        cs += wv;
        float cf = fminf(fmaxf(cs    - sf, -60.f), 60.f);
        float cb = fminf(fmaxf(cprev - sb, -60.f), 60.f);
        float rr = g_r[gi], kk = g_k[gi], vv = g_v[gi];
        size_t go = obase + (size_t)t*K_;
        __nv_bfloat16 hh, ll;
        bsplit(rr * expf( cf), hh, ll); g_rfh[go]=hh; g_rfl[go]=ll;
        bsplit(kk * expf(-cf), hh, ll); g_kfh[go]=hh; g_kfl[go]=ll;
        bsplit(rr * expf(-cb), hh, ll); g_rbh[go]=hh; g_rbl[go]=ll;
        bsplit(kk * expf( cb), hh, ll); g_kbh[go]=hh; g_kbl[go]=ll;
        bsplit(vv, hh, ll);             g_vhh[go]=hh; g_vll[go]=ll;
    }
}

// ---------------- bidirectional attention: R in regs, cp.async K/V pipeline -
#define ASTR 72              // 36 words/row -> conflict-free ldmatrix atoms
#define AARR (64*ASTR)       // elements per array
// A from registers, B (K) from smem
__device__ __forceinline__ void gemm3r(float S[4][4],
    const unsigned (&ah)[4][4], const unsigned (&al)[4][4],
    const __nv_bfloat16* __restrict__ Bhh, const __nv_bfloat16* __restrict__ Bll,
    int nh, int lane)
{
    const int rb = (lane & 7) + ((lane >> 4) & 1) * 8;
    const int cb = ((lane >> 3) & 1) * 8;
    #pragma unroll
    for (int kcb=0; kcb<4; kcb++) {
        int kc = kcb*16;
        #pragma unroll
        for (int ntp=0; ntp<2; ntp++) {
            unsigned bh0,bh1,bh2,bh3, bl0,bl1,bl2,bl3;
            ldsm4(bh0,bh1,bh2,bh3, sm_addr(Bhh + (nh+ntp*16+rb)*ASTR + kc + cb));
            ldsm4(bl0,bl1,bl2,bl3, sm_addr(Bll + (nh+ntp*16+rb)*ASTR + kc + cb));
            mma_bf16(S[ntp*2  ], ah[kcb][0],ah[kcb][1],ah[kcb][2],ah[kcb][3], bh0,bh1);
            mma_bf16(S[ntp*2  ], al[kcb][0],al[kcb][1],al[kcb][2],al[kcb][3], bh0,bh1);
            mma_bf16(S[ntp*2  ], ah[kcb][0],ah[kcb][1],ah[kcb][2],ah[kcb][3], bl0,bl1);
            mma_bf16(S[ntp*2+1], ah[kcb][0],ah[kcb][1],ah[kcb][2],ah[kcb][3], bh2,bh3);
            mma_bf16(S[ntp*2+1], al[kcb][0],al[kcb][1],al[kcb][2],al[kcb][3], bh2,bh3);
            mma_bf16(S[ntp*2+1], ah[kcb][0],ah[kcb][1],ah[kcb][2],ah[kcb][3], bl2,bl3);
        }
    }
}
// A = S (smem), B = V (smem, natural layout, trans ldsm)
__device__ __forceinline__ void gemm3v(float S[4][4],
    const __nv_bfloat16* __restrict__ Ahh, const __nv_bfloat16* __restrict__ All,
    const __nv_bfloat16* __restrict__ Vhh, const __nv_bfloat16* __restrict__ Vll,
    int mi, int nh, int lane)
{
    const int ra = (lane & 7) + ((lane >> 3) & 1) * 8;
    const int ca = ((lane >> 4) & 1) * 8;
    #pragma unroll
    for (int kc=0; kc<64; kc+=16) {
        unsigned ah0,ah1,ah2,ah3, al0,al1,al2,al3;
        ldsm4(ah0,ah1,ah2,ah3, sm_addr(Ahh + (mi+ra)*ASTR + kc + ca));
        ldsm4(al0,al1,al2,al3, sm_addr(All + (mi+ra)*ASTR + kc + ca));
        #pragma unroll
        for (int ntp=0; ntp<2; ntp++) {
            int c0 = nh + ntp*16;
            unsigned bh0,bh1,bh2,bh3, bl0,bl1,bl2,bl3;
            ldsm4t(bh0,bh1,bh2,bh3, sm_addr(Vhh + (kc+ra)*ASTR + c0 + ca));
            ldsm4t(bl0,bl1,bl2,bl3, sm_addr(Vll + (kc+ra)*ASTR + c0 + ca));
            mma_bf16(S[ntp*2  ], ah0,ah1,ah2,ah3, bh0,bh1);
            mma_bf16(S[ntp*2  ], al0,al1,al2,al3, bh0,bh1);
            mma_bf16(S[ntp*2  ], ah0,ah1,ah2,ah3, bl0,bl1);
            mma_bf16(S[ntp*2+1], ah0,ah1,ah2,ah3, bh2,bh3);
            mma_bf16(S[ntp*2+1], al0,al1,al2,al3, bh2,bh3);
            mma_bf16(S[ntp*2+1], ah0,ah1,ah2,ah3, bl2,bl3);
        }
    }
}

__global__ __launch_bounds__(256)
void attn_bf16() {
    extern __shared__ __nv_bfloat16 smb[];
    __nv_bfloat16* Kh[2] = { smb + 0*AARR, smb + 2*AARR };
    __nv_bfloat16* Kl[2] = { smb + 1*AARR, smb + 3*AARR };
    __nv_bfloat16* Vh[2] = { smb + 4*AARR, smb + 6*AARR };
    __nv_bfloat16* Vl[2] = { smb + 5*AARR, smb + 7*AARR };

    int bh = blockIdx.x, it = blockIdx.y;
    int tid = threadIdx.x, lane = tid & 31, w = tid >> 5;
    int g = lane >> 2, t4 = lane & 3;
    int mi = (w & 3) * 16;
    int nh = (w >> 2) * 32;
    size_t base = (size_t)bh * T_ * K_;
    size_t baseW = base >> 1;            // word index into bf16 arrays
    int i0 = it * 64;

    // ---- stage R tiles into buffers, pull A-fragments into registers ----
    {
        const unsigned* rfhW = (const unsigned*)g_rfh;
        const unsigned* rflW = (const unsigned*)g_rfl;
        const unsigned* rbhW = (const unsigned*)g_rbh;
        const unsigned* rblW = (const unsigned*)g_rbl;
        for (int e = tid; e < 2048; e += 256) {
            int r = e >> 5, cw = e & 31;
            size_t gw = baseW + (size_t)(i0 + r)*32 + cw;
            int so = r*ASTR + cw*2;
            *(unsigned*)&Kh[0][so] = rfhW[gw];
            *(unsigned*)&Kl[0][so] = rflW[gw];
            *(unsigned*)&Kh[1][so] = rbhW[gw];
            *(unsigned*)&Kl[1][so] = rblW[gw];
        }
    }
    __syncthreads();
    unsigned afh[4][4], afl[4][4], abh[4][4], abl[4][4];
    {
        const int ra = (lane & 7) + ((lane >> 3) & 1) * 8;
        const int ca = ((lane >> 4) & 1) * 8;
        #pragma unroll
        for (int kcb=0; kcb<4; kcb++) {
            int off = (mi+ra)*ASTR + kcb*16 + ca;
            ldsm4(afh[kcb][0],afh[kcb][1],afh[kcb][2],afh[kcb][3], sm_addr(Kh[0]+off));
            ldsm4(afl[kcb][0],afl[kcb][1],afl[kcb][2],afl[kcb][3], sm_addr(Kl[0]+off));
            ldsm4(abh[kcb][0],abh[kcb][1],abh[kcb][2],abh[kcb][3], sm_addr(Kh[1]+off));
            ldsm4(abl[kcb][0],abl[kcb][1],abl[kcb][2],abl[kcb][3], sm_addr(Kl[1]+off));
        }
    }
    __syncthreads();

    // ---- cp.async K/V pipeline ----
    auto issueKV = [&](int jt2, int b2) {
        int j0 = jt2 * 64;
        const __nv_bfloat16* kh = (jt2 <= it) ? g_kfh : g_kbh;
        const __nv_bfloat16* kl = (jt2 <= it) ? g_kfl : g_kbl;
        #pragma unroll
        for (int i=0;i<2;i++) {
            int e = tid + i*256;
            int r = e >> 3, c8 = (e & 7) * 8;
            size_t gs = base + (size_t)(j0 + r)*K_ + c8;
            int so = r*ASTR + c8;
            CP16(sm_addr(&Kh[b2][so]), kh    + gs);
            CP16(sm_addr(&Kl[b2][so]), kl    + gs);
            CP16(sm_addr(&Vh[b2][so]), g_vhh + gs);
            CP16(sm_addr(&Vl[b2][so]), g_vll + gs);
        }
        CP_COMMIT();
    };
    issueKV(0, 0);

    float o[4][4];
    #pragma unroll
    for (int i=0;i<4;i++)
        #pragma unroll
        for (int j=0;j<4;j++) o[i][j]=0.f;

    int buf = 0;
    for (int jt = 0; jt < 16; jt++) {
        __syncthreads();                 // prev iter done with buf^1
        if (jt + 1 < 16) {
            issueKV(jt + 1, buf ^ 1);
            asm volatile("cp.async.wait_group 1;");
        } else {
            asm volatile("cp.async.wait_group 0;");
        }
        __syncthreads();                 // this tile's K/V visible

        float S[4][4];
        #pragma unroll
        for (int i=0;i<4;i++)
            #pragma unroll
            for (int j=0;j<4;j++) S[i][j]=0.f;

        if (jt <= it) gemm3r(S, afh, afl, Kh[buf], Kl[buf], nh, lane);
        else          gemm3r(S, abh, abl, Kh[buf], Kl[buf], nh, lane);

        if (jt == it) {                  // reload K with backward factors
            __syncthreads();
            {
                const unsigned* kbhW = (const unsigned*)g_kbh;
                const unsigned* kblW = (const unsigned*)g_kbl;
                size_t rowBase = baseW + (size_t)(jt*64)*32;
                for (int e = tid; e < 2048; e += 256) {
                    int r = e >> 5, cw = e & 31;
                    size_t gw = rowBase + (size_t)r*32 + cw;
                    int so = r*ASTR + cw*2;
                    *(unsigned*)&Kh[buf][so] = kbhW[gw];
                    *(unsigned*)&Kl[buf][so] = kblW[gw];
                }
            }
            __syncthreads();
            float Sb[4][4];
            #pragma unroll
            for (int i=0;i<4;i++)
                #pragma unroll
                for (int j=0;j<4;j++) Sb[i][j]=0.f;
            gemm3r(Sb, abh, abl, Kh[buf], Kl[buf], nh, lane);
            #pragma unroll
            for (int nt=0; nt<4; nt++)
                #pragma unroll
                for (int e=0; e<4; e++) {
                    int il = mi + g + ((e>=2)?8:0);
                    int jl = nh + nt*8 + 2*t4 + (e&1);
                    if (il < jl) S[nt][e] = Sb[nt][e];
                }
        }
        __syncthreads();                 // all warps done reading K
        #pragma unroll
        for (int nt=0; nt<4; nt++)
            #pragma unroll
            for (int e=0; e<4; e++) {
                int il = mi + g + ((e>=2)?8:0);
                int jl = nh + nt*8 + 2*t4 + (e&1);
                __nv_bfloat16 h, l;
                bsplit(S[nt][e], h, l);
                Kh[buf][il*ASTR+jl] = h; Kl[buf][il*ASTR+jl] = l;  // S into K buffer
            }
        __syncthreads();
        gemm3v(o, Kh[buf], Kl[buf], Vh[buf], Vl[buf], mi, nh, lane);
        buf ^= 1;
    }
    #pragma unroll
    for (int nt=0; nt<4; nt++)
        #pragma unroll
        for (int e=0; e<4; e++) {
            int il = mi + g + ((e>=2)?8:0);
            int jl = nh + nt*8 + 2*t4 + (e&1);
            g_yh[base + (size_t)(i0 + il)*K_ + jl] = o[nt][e];
        }
}

// ---------------- group-norm + scale/bias + gate (writes split yg) ----------
__global__ __launch_bounds__(512)
void ln_gate_kernel(const float* __restrict__ ln_w,
                    const float* __restrict__ ln_b) {
    int row = blockIdx.x;
    int b = row >> 10, t = row & (T_-1);
    int h = threadIdx.x >> 5;
    int lane = threadIdx.x & 31;
    size_t base = (((size_t)b*H_ + h)*T_ + t)*K_;
    float v0 = g_yh[base + lane*2];
    float v1 = g_yh[base + lane*2 + 1];
    float s = v0 + v1;
    #pragma unroll
    for (int off=16; off>0; off>>=1) s += __shfl_xor_sync(0xffffffffu, s, off);
    float mu = s * (1.f/64.f);
    float d0 = v0 - mu, d1 = v1 - mu;
    float sq = d0*d0 + d1*d1;
    #pragma unroll
    for (int off=16; off>0; off>>=1) sq += __shfl_xor_sync(0xffffffffu, sq, off);
    float inv = rsqrtf(sq*(1.f/64.f) + 6.4e-4f);
    int d = h*K_ + lane*2;
    size_t oo = (size_t)row*D_ + d;
    float y0 = ((d0*inv)*ln_w[d]   + ln_b[d])   * g_gt[oo];
    float y1 = ((d1*inv)*ln_w[d+1] + ln_b[d+1]) * g_gt[oo+1];
    __nv_bfloat16 hh, ll;
    bsplit(y0, hh, ll); g_ygh[oo]   = hh; g_ygl[oo]   = ll;
    bsplit(y1, hh, ll); g_ygh[oo+1] = hh; g_ygl[oo+1] = ll;
}

// ---------------- host launch ------------------------------------------------
extern "C" void kernel_launch(void* const* d_in, const int* in_sizes, int n_in,
                              void* d_out, int out_size) {
    const float* x        = (const float*)d_in[0];
    const float* maa_x    = (const float*)d_in[1];
    const float* maa_w    = (const float*)d_in[2];
    const float* maa_k    = (const float*)d_in[3];
    const float* maa_v    = (const float*)d_in[4];
    const float* maa_r    = (const float*)d_in[5];
    const float* maa_g    = (const float*)d_in[6];
    const float* maa_w1   = (const float*)d_in[7];   // (D, 160)
    const float* maa_w2   = (const float*)d_in[8];   // (5, 32, D)
    const float* tdecay   = (const float*)d_in[9];   // (1,1,D)
    const float* dec_w1   = (const float*)d_in[10];  // (D, 64)
    const float* dec_w2   = (const float*)d_in[11];  // (64, D)
    const float* W_r      = (const float*)d_in[12];
    const float* W_k      = (const float*)d_in[13];
    const float* W_v      = (const float*)d_in[14];
    const float* W_g      = (const float*)d_in[15];
    const float* W_o      = (const float*)d_in[16];
    const float* ln_w     = (const float*)d_in[17];
    const float* ln_b     = (const float*)d_in[18];
    float* out = (float*)d_out;

    float *p_xmix, *p_xxx, *p_xw, *p_r, *p_k, *p_v, *p_gt, *p_w, *p_wtmp;
    __nv_bfloat16 *p_xmh, *p_xml, *p_Wh, *p_Wl, *p_ygh, *p_ygl;
    cudaGetSymbolAddress((void**)&p_xmix, g_xmix);
    cudaGetSymbolAddress((void**)&p_xxx,  g_xxx);
    cudaGetSymbolAddress((void**)&p_xw,   g_xw);
    cudaGetSymbolAddress((void**)&p_r,    g_r);
    cudaGetSymbolAddress((void**)&p_k,    g_k);
    cudaGetSymbolAddress((void**)&p_v,    g_v);
    cudaGetSymbolAddress((void**)&p_gt,   g_gt);
    cudaGetSymbolAddress((void**)&p_w,    g_w);
    cudaGetSymbolAddress((void**)&p_wtmp, g_wtmp);
    cudaGetSymbolAddress((void**)&p_xmh,  g_xmh);
    cudaGetSymbolAddress((void**)&p_xml,  g_xml);
    cudaGetSymbolAddress((void**)&p_Wh,   g_Wh);
    cudaGetSymbolAddress((void**)&p_Wl,   g_Wl);
    cudaGetSymbolAddress((void**)&p_ygh,  g_ygh);
    cudaGetSymbolAddress((void**)&p_ygl,  g_ygl);

    // 1) dxprev + xmix
    prep_kernel<<<(BTD+255)/256, 256>>>(x, maa_x);

    // 2) split all 5 big weights (one kernel, vectorized)
    split5_kernel<<<(5*DD_/4 + 255)/256, 256>>>(W_r, W_k, W_v, W_g, W_o);

    // 3) xxx = tanh(xmix @ maa_w1)    (tf32)
    mma_gemm<EP_TANH><<<dim3(3,32), 256>>>(
        p_xmix, D_, maa_w1, 160, p_xxx, 160, BT_, 160, D_, nullptr);

    // 4) all 5 mixes, one f per grid.z; writes fp32 xw + split xk/xv/xr/xg
    mix_fused2<<<dim3(16,32,5), 256>>>(
        x, maa_w2, maa_w, maa_k, maa_v, maa_r, maa_g);

    // 5) all 4 projections in one batched launch (2-stage, 48 KB smem)
    {
        GemmBatch batch;
        batch.j[0] = { p_xmh + 2*(size_t)BTD, p_xml + 2*(size_t)BTD,
                       p_Wh + 0*(size_t)DD_,  p_Wl + 0*(size_t)DD_, p_r,  0 };
        batch.j[1] = { p_xmh + 0*(size_t)BTD, p_xml + 0*(size_t)BTD,
                       p_Wh + 1*(size_t)DD_,  p_Wl + 1*(size_t)DD_, p_k,  0 };
        batch.j[2] = { p_xmh + 1*(size_t)BTD, p_xml + 1*(size_t)BTD,
                       p_Wh + 2*(size_t)DD_,  p_Wl + 2*(size_t)DD_, p_v,  0 };
        batch.j[3] = { p_xmh + 3*(size_t)BTD, p_xml + 3*(size_t)BTD,
                       p_Wh + 3*(size_t)DD_,  p_Wl + 3*(size_t)DD_, p_gt, 1 };
        bgemm2<<<dim3(8,32,4), 256>>>(batch);
    }

    // 6) w = time_decay + tanh(xw @ dec_w1) @ dec_w2   (tf32 tensor cores)
    mma_gemm<EP_TANH><<<dim3(1,32), 256>>>(
        p_xw, D_, dec_w1, 64, p_wtmp, 64, BT_, 64, D_, nullptr);
    mma_gemm<EP_BIAS><<<dim3(16,32), 256>>>(
        p_wtmp, 64, dec_w2, D_, p_w, D_, BT_, D_, 64, tdecay);

    // 7) cumsum prefix (pass 1) + exp factors full-chip (pass 2)
    headprep_sums<<<B_*H_, 1024>>>();
    headprep2<<<dim3(B_*H_, 16), 256>>>();

    // 8) bidirectional attention (R in regs, cp.async double-buffered K/V)
    static const int ATTN_SMEM = 8*AARR*2;   // 73728 B
    cudaFuncSetAttribute(attn_bf16,
                         cudaFuncAttributeMaxDynamicSharedMemorySize, ATTN_SMEM);
    attn_bf16<<<dim3(B_*H_, 16), 256, ATTN_SMEM>>>();

    // 9) group-norm + gate (writes split yg)
    ln_gate_kernel<<<BT_, 512>>>(ln_w, ln_b);

    // 10) out = yg @ W_o^T (same batched kernel, single job)
    {
        GemmBatch batch;
        batch.j[0] = { p_ygh, p_ygl, p_Wh + 4*(size_t)DD_, p_Wl + 4*(size_t)DD_,
                       out, 0 };
        batch.j[1] = batch.j[0];
        batch.j[2] = batch.j[0];
        batch.j[3] = batch.j[0];
        bgemm2<<<dim3(8,32,1), 256>>>(batch);
    }
}

// round 16
// speedup vs baseline: 1.0730x; 1.0730x over previous
#include <cuda_runtime.h>
#include <cuda_bf16.h>
#include <math.h>

#define B_ 4
#define T_ 1024
#define D_ 1024
#define H_ 16
#define K_ 64
#define BT_ (B_*T_)        // 4096
#define BTD (BT_*D_)       // 4194304
#define DD_ (D_*D_)

// ---------------- scratch (static device globals; no runtime alloc) --------
__device__ float g_dx[BTD];
__device__ float g_xmix[BTD];
__device__ float g_xxx[BT_*160];
__device__ float g_xw[BTD];             // fp32 xw for decay chain
__device__ float g_r[BTD], g_k[BTD], g_v[BTD], g_gt[BTD], g_w[BTD];
__device__ float g_wtmp[BT_*64];
__device__ float g_yh[BTD];
__device__ float g_pfx[64*64*64];       // [bh][subchunk16][kx] exclusive prefix
__device__ float g_shfA[64*64], g_shbA[64*64];

__device__ __nv_bfloat16 g_xmh[4*BTD], g_xml[4*BTD];   // k,v,r,g mixes (split)
__device__ __nv_bfloat16 g_Wh[5*DD_],  g_Wl[5*DD_];    // W_r,W_k,W_v,W_g,W_o
__device__ __nv_bfloat16 g_rfh[BTD], g_rfl[BTD];
__device__ __nv_bfloat16 g_kfh[BTD], g_kfl[BTD];
__device__ __nv_bfloat16 g_rbh[BTD], g_rbl[BTD];
__device__ __nv_bfloat16 g_kbh[BTD], g_kbl[BTD];
__device__ __nv_bfloat16 g_vhh[BTD], g_vll[BTD];
__device__ __nv_bfloat16 g_ygh[BTD], g_ygl[BTD];

enum { EP_NONE=0, EP_TANH=1, EP_SILU=2, EP_BIAS=3 };

// ---------------- helpers ----------------------------------------------------
__device__ __forceinline__ unsigned tf32_of(float x) {
    unsigned u; asm("cvt.rna.tf32.f32 %0, %1;" : "=r"(u) : "f"(x)); return u;
}
__device__ __forceinline__ float tf32f(float x) {
    return __uint_as_float(tf32_of(x));
}
__device__ __forceinline__ void mma_tf32(float c[4], unsigned a0, unsigned a1,
                                         unsigned a2, unsigned a3,
                                         unsigned b0, unsigned b1) {
    asm volatile(
        "mma.sync.aligned.m16n8k8.row.col.f32.tf32.tf32.f32 "
        "{%0,%1,%2,%3},{%4,%5,%6,%7},{%8,%9},{%0,%1,%2,%3};"
        : "+f"(c[0]), "+f"(c[1]), "+f"(c[2]), "+f"(c[3])
        : "r"(a0), "r"(a1), "r"(a2), "r"(a3), "r"(b0), "r"(b1));
}
__device__ __forceinline__ void mma_bf16(float c[4], unsigned a0, unsigned a1,
                                         unsigned a2, unsigned a3,
                                         unsigned b0, unsigned b1) {
    asm volatile(
        "mma.sync.aligned.m16n8k16.row.col.f32.bf16.bf16.f32 "
        "{%0,%1,%2,%3},{%4,%5,%6,%7},{%8,%9},{%0,%1,%2,%3};"
        : "+f"(c[0]), "+f"(c[1]), "+f"(c[2]), "+f"(c[3])
        : "r"(a0), "r"(a1), "r"(a2), "r"(a3), "r"(b0), "r"(b1));
}
__device__ __forceinline__ void bsplit(float x, __nv_bfloat16& h, __nv_bfloat16& l) {
    h = __float2bfloat16(x);
    l = __float2bfloat16(x - __bfloat162float(h));
}
__device__ __forceinline__ unsigned sm_addr(const void* p) {
    return (unsigned)__cvta_generic_to_shared(p);
}
__device__ __forceinline__ void ldsm4(unsigned& r0, unsigned& r1,
                                      unsigned& r2, unsigned& r3, unsigned a) {
    asm volatile("ldmatrix.sync.aligned.m8n8.x4.shared.b16 {%0,%1,%2,%3}, [%4];"
        : "=r"(r0), "=r"(r1), "=r"(r2), "=r"(r3) : "r"(a));
}
__device__ __forceinline__ void ldsm4t(unsigned& r0, unsigned& r1,
                                       unsigned& r2, unsigned& r3, unsigned a) {
    asm volatile("ldmatrix.sync.aligned.m8n8.x4.trans.shared.b16 {%0,%1,%2,%3}, [%4];"
        : "=r"(r0), "=r"(r1), "=r"(r2), "=r"(r3) : "r"(a));
}
#define CP16(dst, src) asm volatile( \
    "cp.async.cg.shared.global [%0], [%1], 16;" :: "r"(dst), "l"(src))
#define CP_COMMIT() asm volatile("cp.async.commit_group;")

// ---------------- prep: dxprev + xmix ---------------------------------------
__global__ void prep_kernel(const float* __restrict__ x,
                            const float* __restrict__ maa_x) {
    int idx = blockIdx.x*256 + threadIdx.x;
    if (idx >= BTD) return;
    int d = idx & (D_-1);
    int t = (idx >> 10) & (T_-1);
    float xc = x[idx];
    float left  = (t > 0)     ? x[idx - D_] : 0.f;
    float right = (t < T_-1)  ? x[idx + D_] : 0.f;
    float dx = 0.5f*(left + right) - xc;
    g_dx[idx]   = dx;
    g_xmix[idx] = xc + dx * maa_x[d];
}

// ---------------- split all 5 weights into bf16 hi/lo (vectorized) ----------
__global__ void split5_kernel(const float* __restrict__ w0,
                              const float* __restrict__ w1,
                              const float* __restrict__ w2,
                              const float* __restrict__ w3,
                              const float* __restrict__ w4) {
    const float* srcs[5] = {w0, w1, w2, w3, w4};
    size_t q = (size_t)blockIdx.x*256 + threadIdx.x;   // float4 index
    const size_t QW = DD_/4;
    if (q >= 5*QW) return;
    int wi = (int)(q / QW);
    size_t r = q - (size_t)wi*QW;
    float4 v = ((const float4*)srcs[wi])[r];
    __nv_bfloat16 h0,l0,h1,l1,h2,l2,h3,l3;
    bsplit(v.x,h0,l0); bsplit(v.y,h1,l1); bsplit(v.z,h2,l2); bsplit(v.w,h3,l3);
    __nv_bfloat162* Hp = (__nv_bfloat162*)(g_Wh + (size_t)wi*DD_ + r*4);
    __nv_bfloat162* Lp = (__nv_bfloat162*)(g_Wl + (size_t)wi*DD_ + r*4);
    Hp[0] = __halves2bfloat162(h0,h1); Hp[1] = __halves2bfloat162(h2,h3);
    Lp[0] = __halves2bfloat162(l0,l1); Lp[1] = __halves2bfloat162(l2,l3);
}

// ---------------- tf32 tensor-core GEMM (NN), with TANH/BIAS epilogues ------
template<int EP>
__global__ __launch_bounds__(256)
void mma_gemm(const float* __restrict__ A, int lda,
              const float* __restrict__ Bm, int ldb,
              float* __restrict__ C, int ldc,
              int M, int N, int Kd,
              const float* __restrict__ bias)
{
    __shared__ float As[128][20];
    __shared__ float Bs[64][20];
    const int tid  = threadIdx.x;
    const int lane = tid & 31, w = tid >> 5;
    const int g = lane >> 2, t4 = lane & 3;
    const int m0 = blockIdx.y * 128, n0 = blockIdx.x * 64;
    const int mw = w * 16;

    float acc[8][4];
    #pragma unroll
    for (int i=0;i<8;i++)
        #pragma unroll
        for (int j=0;j<4;j++) acc[i][j]=0.f;

    for (int k0 = 0; k0 < Kd; k0 += 16) {
        {
            int r = tid >> 1, c = (tid & 1) * 8;
            const float* ap = A + (size_t)(m0 + r) * lda + k0 + c;
            float4 v0 = *(const float4*)(ap);
            float4 v1 = *(const float4*)(ap + 4);
            As[r][c+0]=tf32f(v0.x); As[r][c+1]=tf32f(v0.y);
            As[r][c+2]=tf32f(v0.z); As[r][c+3]=tf32f(v0.w);
            As[r][c+4]=tf32f(v1.x); As[r][c+5]=tf32f(v1.y);
            As[r][c+6]=tf32f(v1.z); As[r][c+7]=tf32f(v1.w);
        }
        {
            int n = tid & 63, kk = tid >> 6;
            int gn = n0 + n;
            #pragma unroll
            for (int q=0;q<4;q++) {
                int gk = k0 + kk + q*4;
                float v = (gn < N) ? Bm[(size_t)gk*ldb + gn] : 0.f;
                Bs[n][kk + q*4] = tf32f(v);
            }
        }
        __syncthreads();
        #pragma unroll
        for (int kc=0; kc<16; kc+=8) {
            unsigned a0 = __float_as_uint(As[mw+g  ][kc+t4  ]);
            unsigned a1 = __float_as_uint(As[mw+g+8][kc+t4  ]);
            unsigned a2 = __float_as_uint(As[mw+g  ][kc+t4+4]);
            unsigned a3 = __float_as_uint(As[mw+g+8][kc+t4+4]);
            #pragma unroll
            for (int nt=0; nt<8; nt++) {
                unsigned b0 = __float_as_uint(Bs[nt*8+g][kc+t4  ]);
                unsigned b1 = __float_as_uint(Bs[nt*8+g][kc+t4+4]);
                mma_tf32(acc[nt], a0,a1,a2,a3, b0,b1);
            }
        }
        __syncthreads();
    }
    #pragma unroll
    for (int nt=0; nt<8; nt++) {
        #pragma unroll
        for (int e=0; e<4; e++) {
            int m = m0 + mw + g + ((e>=2)?8:0);
            int n = n0 + nt*8 + 2*t4 + (e&1);
            if (n >= N) continue;
            float v = acc[nt][e];
            if (EP == EP_TANH)      v = tanhf(v);
            else if (EP == EP_BIAS) v = v + bias[n];
            C[(size_t)m*ldc + n] = v;
        }
    }
}

// ---------------- batched bf16x3 GEMM, NT, 128x128, 2-stage cp.async+ldsm ---
struct GemmJob {
    const __nv_bfloat16 *Ah, *Al, *Bh, *Bl;
    float* C;
    int silu;
};
struct GemmBatch { GemmJob j[4]; };

__global__ __launch_bounds__(256)
void bgemm2(GemmBatch batch)
{
    __shared__ __nv_bfloat16 sA[2][2][128][24];   // [buf][h/l][m][k]
    __shared__ __nv_bfloat16 sB[2][2][128][24];   // [buf][h/l][n][k]
    const GemmJob job = batch.j[blockIdx.z];
    const int tid = threadIdx.x, lane = tid & 31, w = tid >> 5;
    const int g = lane >> 2, t4 = lane & 3;
    const int m0 = blockIdx.y * 128, n0 = blockIdx.x * 128;
    const int wm = (w & 3) * 32, wn = (w >> 2) * 64;
    const int ra = (lane & 7) + ((lane >> 3) & 1) * 8;
    const int ca = ((lane >> 4) & 1) * 8;
    const int rb = (lane & 7) + ((lane >> 4) & 1) * 8;
    const int cb = ((lane >> 3) & 1) * 8;

    float acc[2][8][4];
    #pragma unroll
    for (int a=0;a<2;a++)
        #pragma unroll
        for (int i=0;i<8;i++)
            #pragma unroll
            for (int j=0;j<4;j++) acc[a][i][j]=0.f;

    const int r = tid >> 1, c0 = (tid & 1) * 8;
    const __nv_bfloat16* srcAh = job.Ah + (size_t)(m0 + r)*D_ + c0;
    const __nv_bfloat16* srcAl = job.Al + (size_t)(m0 + r)*D_ + c0;
    const __nv_bfloat16* srcBh = job.Bh + (size_t)(n0 + r)*D_ + c0;
    const __nv_bfloat16* srcBl = job.Bl + (size_t)(n0 + r)*D_ + c0;

    auto issue = [&](int s, int buf) {
        int k0 = s * 16;
        CP16(sm_addr(&sA[buf][0][r][c0]), srcAh + k0);
        CP16(sm_addr(&sA[buf][1][r][c0]), srcAl + k0);
        CP16(sm_addr(&sB[buf][0][r][c0]), srcBh + k0);
        CP16(sm_addr(&sB[buf][1][r][c0]), srcBl + k0);
        CP_COMMIT();
    };
    issue(0, 0);

    int buf = 0;
    for (int s = 0; s < 64; s++) {
        if (s + 1 < 64) {
            issue(s + 1, buf ^ 1);
            asm volatile("cp.async.wait_group 1;");
        } else {
            asm volatile("cp.async.wait_group 0;");
        }
        __syncthreads();

        unsigned ah[2][4], al[2][4];
        #pragma unroll
        for (int ms=0; ms<2; ms++) {
            ldsm4(ah[ms][0], ah[ms][1], ah[ms][2], ah[ms][3],
                  sm_addr(&sA[buf][0][wm + ms*16 + ra][ca]));
            ldsm4(al[ms][0], al[ms][1], al[ms][2], al[ms][3],
                  sm_addr(&sA[buf][1][wm + ms*16 + ra][ca]));
        }
        #pragma unroll
        for (int ntp=0; ntp<4; ntp++) {
            unsigned bh0,bh1,bh2,bh3, bl0,bl1,bl2,bl3;
            ldsm4(bh0,bh1,bh2,bh3, sm_addr(&sB[buf][0][wn + ntp*16 + rb][cb]));
            ldsm4(bl0,bl1,bl2,bl3, sm_addr(&sB[buf][1][wn + ntp*16 + rb][cb]));
            #pragma unroll
            for (int ms=0; ms<2; ms++) {
                mma_bf16(acc[ms][ntp*2  ], ah[ms][0],ah[ms][1],ah[ms][2],ah[ms][3], bh0,bh1);
                mma_bf16(acc[ms][ntp*2  ], al[ms][0],al[ms][1],al[ms][2],al[ms][3], bh0,bh1);
                mma_bf16(acc[ms][ntp*2  ], ah[ms][0],ah[ms][1],ah[ms][2],ah[ms][3], bl0,bl1);
                mma_bf16(acc[ms][ntp*2+1], ah[ms][0],ah[ms][1],ah[ms][2],ah[ms][3], bh2,bh3);
                mma_bf16(acc[ms][ntp*2+1], al[ms][0],al[ms][1],al[ms][2],al[ms][3], bh2,bh3);
                mma_bf16(acc[ms][ntp*2+1], ah[ms][0],ah[ms][1],ah[ms][2],ah[ms][3], bl2,bl3);
            }
        }
        __syncthreads();
        buf ^= 1;
    }

    #pragma unroll
    for (int ms=0; ms<2; ms++)
        #pragma unroll
        for (int nt=0; nt<8; nt++)
            #pragma unroll
            for (int pr=0; pr<2; pr++) {
                int mm = m0 + wm + ms*16 + g + pr*8;
                int nn = n0 + wn + nt*8 + 2*t4;
                float v0 = acc[ms][nt][pr*2], v1 = acc[ms][nt][pr*2+1];
                if (job.silu) {
                    v0 = v0 / (1.f + expf(-v0));
                    v1 = v1 / (1.f + expf(-v1));
                }
                float2 vv = make_float2(v0, v1);
                *(float2*)&job.C[(size_t)mm*D_ + nn] = vv;
            }
}

// ---------------- mix (one f per blockIdx.z): x + dx*(maa_f + xxx_f@w2_f) ---
// B stored transposed [n][k] (stride 36) -> conflict-free fragment loads.
__global__ __launch_bounds__(256)
void mix_fused2(const float* __restrict__ x,
                const float* __restrict__ w2,      // (5,32,1024)
                const float* __restrict__ mw_, const float* __restrict__ mk_,
                const float* __restrict__ mv_, const float* __restrict__ mr_,
                const float* __restrict__ mg_)
{
    __shared__ float As[128][36];
    __shared__ float Bs[64][36];      // [n][k]
    const int tid = threadIdx.x, lane = tid & 31, w = tid >> 5;
    const int g = lane >> 2, t4 = lane & 3;
    const int m0 = blockIdx.y * 128, n0 = blockIdx.x * 64;
    const int f  = blockIdx.z;
    const int mw2 = w * 16;
    const float* maas[5] = {mw_, mk_, mv_, mr_, mg_};
    const float* maa = maas[f];

    {
        int r = tid >> 1, c0 = (tid & 1) * 16;
        const float* ap = g_xxx + (size_t)(m0 + r) * 160 + f*32 + c0;
        #pragma unroll
        for (int q=0;q<4;q++) {
            float4 v = *(const float4*)(ap + q*4);
            As[r][c0+q*4+0]=tf32f(v.x); As[r][c0+q*4+1]=tf32f(v.y);
            As[r][c0+q*4+2]=tf32f(v.z); As[r][c0+q*4+3]=tf32f(v.w);
        }
    }
    {
        int kk = tid >> 3, c0 = (tid & 7) * 8;
        const float* bp = w2 + (size_t)f*32*D_ + (size_t)kk*D_ + n0 + c0;
        #pragma unroll
        for (int q=0;q<2;q++) {
            float4 v = *(const float4*)(bp + q*4);
            Bs[c0+q*4+0][kk]=tf32f(v.x); Bs[c0+q*4+1][kk]=tf32f(v.y);
            Bs[c0+q*4+2][kk]=tf32f(v.z); Bs[c0+q*4+3][kk]=tf32f(v.w);
        }
    }
    __syncthreads();

    float acc[8][4];
    #pragma unroll
    for (int i=0;i<8;i++)
        #pragma unroll
        for (int j=0;j<4;j++) acc[i][j]=0.f;
    #pragma unroll
    for (int kc=0; kc<32; kc+=8) {
        unsigned a0 = __float_as_uint(As[mw2+g  ][kc+t4  ]);
        unsigned a1 = __float_as_uint(As[mw2+g+8][kc+t4  ]);
        unsigned a2 = __float_as_uint(As[mw2+g  ][kc+t4+4]);
        unsigned a3 = __float_as_uint(As[mw2+g+8][kc+t4+4]);
        #pragma unroll
        for (int nt=0; nt<8; nt++) {
            unsigned b0 = __float_as_uint(Bs[nt*8+g][kc+t4  ]);
            unsigned b1 = __float_as_uint(Bs[nt*8+g][kc+t4+4]);
            mma_tf32(acc[nt], a0,a1,a2,a3, b0,b1);
        }
    }
    #pragma unroll
    for (int nt=0; nt<8; nt++) {
        #pragma unroll
        for (int pr=0; pr<2; pr++) {
            int ml = mw2 + g + pr*8;
            int nl = nt*8 + 2*t4;
            size_t idx = (size_t)(m0+ml)*D_ + n0 + nl;
            float2 xv  = *(const float2*)&x[idx];
            float2 dxv = *(const float2*)&g_dx[idx];
            float v0 = acc[nt][pr*2],   v1 = acc[nt][pr*2+1];
            float r0 = xv.x + dxv.x*(maa[n0+nl]   + v0);
            float r1 = xv.y + dxv.y*(maa[n0+nl+1] + v1);
            if (f == 0) {
                *(float2*)&g_xw[idx] = make_float2(r0, r1);
            } else {
                __nv_bfloat16 h0,l0,h1,l1;
                bsplit(r0,h0,l0); bsplit(r1,h1,l1);
                *(__nv_bfloat162*)&g_xmh[(size_t)(f-1)*BTD + idx] = __halves2bfloat162(h0,h1);
                *(__nv_bfloat162*)&g_xml[(size_t)(f-1)*BTD + idx] = __halves2bfloat162(l0,l1);
            }
        }
    }
}

// ---------------- headprep pass 1: 16-step-granular prefix sums -------------
__global__ __launch_bounds__(1024)
void headprep_sums() {
    int bh = blockIdx.x;
    int b = bh >> 4, h = bh & 15;
    int tid = threadIdx.x;
    int c = tid >> 6, kx = tid & 63;     // c: 0..15 (64-step chunk)
    __shared__ float sub[64][64];        // [subchunk16][kx]
    __shared__ float w512[64];
    const size_t ibase = (size_t)b*T_*D_ + (size_t)h*K_ + kx;
    #pragma unroll
    for (int q=0; q<4; q++) {
        float s = 0.f;
        #pragma unroll 4
        for (int i=0; i<16; i++) {
            int t = c*64 + q*16 + i;
            float wv = -expf(g_w[ibase + (size_t)t*D_]);
            if (t == 512) w512[kx] = wv;
            s += wv;
        }
        sub[c*4+q][kx] = s;
    }
    __syncthreads();
    if (tid < 64) {
        float run = 0.f, shb = 0.f;
        #pragma unroll
        for (int sc=0; sc<64; sc++) {
            if (sc == 32) shb = run;
            g_pfx[((size_t)bh*64 + sc)*64 + tid] = run;
            run += sub[sc][tid];
        }
        g_shbA[bh*64 + tid] = shb;
        g_shfA[bh*64 + tid] = shb + w512[tid];
    }
}

// ---------------- headprep pass 2: exp factors, full-chip parallel ----------
__global__ __launch_bounds__(256)
void headprep2() {
    int bh = blockIdx.x, blkc = blockIdx.y;        // blkc: 0..15
    int b = bh >> 4, h = bh & 15;
    int tid = threadIdx.x;
    int q = tid >> 6, kx = tid & 63;               // q: 0..3
    int sc = blkc*4 + q;
    int t0 = sc*16;
    const size_t ibase = (size_t)b*T_*D_ + (size_t)h*K_ + kx;
    float cs = g_pfx[((size_t)bh*64 + sc)*64 + kx];
    float sf = g_shfA[bh*64 + kx], sb = g_shbA[bh*64 + kx];
    size_t obase = (size_t)bh*T_*K_ + kx;
    #pragma unroll 4
    for (int i=0; i<16; i++) {
        int t = t0 + i;
        size_t gi = ibase + (size_t)t*D_;
        float wv = -expf(g_w[gi]);
        float cprev = cs;
        cs += wv;
        float cf = fminf(fmaxf(cs    - sf, -60.f), 60.f);
        float cb = fminf(fmaxf(cprev - sb, -60.f), 60.f);
        float rr = g_r[gi], kk = g_k[gi], vv = g_v[gi];
        size_t go = obase + (size_t)t*K_;
        __nv_bfloat16 hh, ll;
        bsplit(rr * expf( cf), hh, ll); g_rfh[go]=hh; g_rfl[go]=ll;
        bsplit(kk * expf(-cf), hh, ll); g_kfh[go]=hh; g_kfl[go]=ll;
        bsplit(rr * expf(-cb), hh, ll); g_rbh[go]=hh; g_rbl[go]=ll;
        bsplit(kk * expf( cb), hh, ll); g_kbh[go]=hh; g_kbl[go]=ll;
        bsplit(vv, hh, ll);             g_vhh[go]=hh; g_vll[go]=ll;
    }
}

// ---------------- bidirectional attention, bf16x3 + ldmatrix, 8 smem arrays -
#define ASTR 72              // 36 words/row -> conflict-free ldmatrix atoms
#define AARR (64*ASTR)       // elements per array
__device__ __forceinline__ void gemm3(float S[4][4],
    const __nv_bfloat16* __restrict__ Ahh, const __nv_bfloat16* __restrict__ All,
    const __nv_bfloat16* __restrict__ Bhh, const __nv_bfloat16* __restrict__ Bll,
    int mi, int nh, int lane)
{
    const int ra = (lane & 7) + ((lane >> 3) & 1) * 8;
    const int ca = ((lane >> 4) & 1) * 8;
    const int rb = (lane & 7) + ((lane >> 4) & 1) * 8;
    const int cb = ((lane >> 3) & 1) * 8;
    #pragma unroll
    for (int kc=0; kc<64; kc+=16) {
        unsigned ah0,ah1,ah2,ah3, al0,al1,al2,al3;
        ldsm4(ah0,ah1,ah2,ah3, sm_addr(Ahh + (mi+ra)*ASTR + kc + ca));
        ldsm4(al0,al1,al2,al3, sm_addr(All + (mi+ra)*ASTR + kc + ca));
        #pragma unroll
        for (int ntp=0; ntp<2; ntp++) {
            unsigned bh0,bh1,bh2,bh3, bl0,bl1,bl2,bl3;
            ldsm4(bh0,bh1,bh2,bh3, sm_addr(Bhh + (nh+ntp*16+rb)*ASTR + kc + cb));
            ldsm4(bl0,bl1,bl2,bl3, sm_addr(Bll + (nh+ntp*16+rb)*ASTR + kc + cb));
            mma_bf16(S[ntp*2  ], ah0,ah1,ah2,ah3, bh0,bh1);
            mma_bf16(S[ntp*2  ], al0,al1,al2,al3, bh0,bh1);
            mma_bf16(S[ntp*2  ], ah0,ah1,ah2,ah3, bl0,bl1);
            mma_bf16(S[ntp*2+1], ah0,ah1,ah2,ah3, bh2,bh3);
            mma_bf16(S[ntp*2+1], al0,al1,al2,al3, bh2,bh3);
            mma_bf16(S[ntp*2+1], ah0,ah1,ah2,ah3, bl2,bl3);
        }
    }
}
__device__ __forceinline__ void gemm3v(float S[4][4],
    const __nv_bfloat16* __restrict__ Ahh, const __nv_bfloat16* __restrict__ All,
    const __nv_bfloat16* __restrict__ Vhh, const __nv_bfloat16* __restrict__ Vll,
    int mi, int nh, int lane)
{
    const int ra = (lane & 7) + ((lane >> 3) & 1) * 8;
    const int ca = ((lane >> 4) & 1) * 8;
    #pragma unroll
    for (int kc=0; kc<64; kc+=16) {
        unsigned ah0,ah1,ah2,ah3, al0,al1,al2,al3;
        ldsm4(ah0,ah1,ah2,ah3, sm_addr(Ahh + (mi+ra)*ASTR + kc + ca));
        ldsm4(al0,al1,al2,al3, sm_addr(All + (mi+ra)*ASTR + kc + ca));
        #pragma unroll
        for (int ntp=0; ntp<2; ntp++) {
            int c0 = nh + ntp*16;
            unsigned bh0,bh1,bh2,bh3, bl0,bl1,bl2,bl3;
            ldsm4t(bh0,bh1,bh2,bh3, sm_addr(Vhh + (kc+ra)*ASTR + c0 + ca));
            ldsm4t(bl0,bl1,bl2,bl3, sm_addr(Vll + (kc+ra)*ASTR + c0 + ca));
            mma_bf16(S[ntp*2  ], ah0,ah1,ah2,ah3, bh0,bh1);
            mma_bf16(S[ntp*2  ], al0,al1,al2,al3, bh0,bh1);
            mma_bf16(S[ntp*2  ], ah0,ah1,ah2,ah3, bl0,bl1);
            mma_bf16(S[ntp*2+1], ah0,ah1,ah2,ah3, bh2,bh3);
            mma_bf16(S[ntp*2+1], al0,al1,al2,al3, bh2,bh3);
            mma_bf16(S[ntp*2+1], ah0,ah1,ah2,ah3, bl2,bl3);
        }
    }
}

__global__ __launch_bounds__(256)
void attn_bf16() {
    extern __shared__ __nv_bfloat16 smb[];
    __nv_bfloat16* Rfh = smb + 0*AARR;  __nv_bfloat16* Rfl = smb + 1*AARR;
    __nv_bfloat16* Rbh = smb + 2*AARR;  __nv_bfloat16* Rbl = smb + 3*AARR;
    __nv_bfloat16* Ksh = smb + 4*AARR;  __nv_bfloat16* Ksl = smb + 5*AARR; // K, later S
    __nv_bfloat16* Vsh = smb + 6*AARR;  __nv_bfloat16* Vsl = smb + 7*AARR;

    int bh = blockIdx.x, it = blockIdx.y;
    int tid = threadIdx.x, lane = tid & 31, w = tid >> 5;
    int g = lane >> 2, t4 = lane & 3;
    int mi = (w & 3) * 16;
    int nh = (w >> 2) * 32;
    size_t base = (size_t)bh * T_ * K_;
    size_t baseW = base >> 1;            // word index into bf16 arrays
    int i0 = it * 64;

    {
        const unsigned* rfhW = (const unsigned*)g_rfh;
        const unsigned* rflW = (const unsigned*)g_rfl;
        const unsigned* rbhW = (const unsigned*)g_rbh;
        const unsigned* rblW = (const unsigned*)g_rbl;
        for (int e = tid; e < 2048; e += 256) {
            int r = e >> 5, cw = e & 31;
            size_t gw = baseW + (size_t)(i0 + r)*32 + cw;
            int so = r*ASTR + cw*2;
            *(unsigned*)&Rfh[so] = rfhW[gw];
            *(unsigned*)&Rfl[so] = rflW[gw];
            *(unsigned*)&Rbh[so] = rbhW[gw];
            *(unsigned*)&Rbl[so] = rblW[gw];
        }
    }

    float o[4][4];
    #pragma unroll
    for (int i=0;i<4;i++)
        #pragma unroll
        for (int j=0;j<4;j++) o[i][j]=0.f;

    for (int jt = 0; jt < 16; jt++) {
        __syncthreads();                 // K/V/S buffers free from prior iter
        int j0 = jt * 64;
        size_t rowBase = baseW + (size_t)j0*32;
        {
            const unsigned* vhhW = (const unsigned*)g_vhh;
            const unsigned* vllW = (const unsigned*)g_vll;
            const unsigned* khW = (jt <= it) ? (const unsigned*)g_kfh
                                             : (const unsigned*)g_kbh;
            const unsigned* klW = (jt <= it) ? (const unsigned*)g_kfl
                                             : (const unsigned*)g_kbl;
            for (int e = tid; e < 2048; e += 256) {
                int r = e >> 5, cw = e & 31;
                size_t gw = rowBase + (size_t)r*32 + cw;
                int so = r*ASTR + cw*2;
                *(unsigned*)&Vsh[so] = vhhW[gw];
                *(unsigned*)&Vsl[so] = vllW[gw];
                *(unsigned*)&Ksh[so] = khW[gw];
                *(unsigned*)&Ksl[so] = klW[gw];
            }
        }
        __syncthreads();

        float S[4][4];
        #pragma unroll
        for (int i=0;i<4;i++)
            #pragma unroll
            for (int j=0;j<4;j++) S[i][j]=0.f;

        if (jt <= it) gemm3(S, Rfh, Rfl, Ksh, Ksl, mi, nh, lane);
        else          gemm3(S, Rbh, Rbl, Ksh, Ksl, mi, nh, lane);

        if (jt == it) {                  // reload K with backward factors
            __syncthreads();
            {
                const unsigned* kbhW = (const unsigned*)g_kbh;
                const unsigned* kblW = (const unsigned*)g_kbl;
                for (int e = tid; e < 2048; e += 256) {
                    int r = e >> 5, cw = e & 31;
                    size_t gw = rowBase + (size_t)r*32 + cw;
                    int so = r*ASTR + cw*2;
                    *(unsigned*)&Ksh[so] = kbhW[gw];
                    *(unsigned*)&Ksl[so] = kblW[gw];
                }
            }
            __syncthreads();
            float Sb[4][4];
            #pragma unroll
            for (int i=0;i<4;i++)
                #pragma unroll
                for (int j=0;j<4;j++) Sb[i][j]=0.f;
            gemm3(Sb, Rbh, Rbl, Ksh, Ksl, mi, nh, lane);
            #pragma unroll
            for (int nt=0; nt<4; nt++)
                #pragma unroll
                for (int e=0; e<4; e++) {
                    int il = mi + g + ((e>=2)?8:0);
                    int jl = nh + nt*8 + 2*t4 + (e&1);
                    if (il < jl) S[nt][e] = Sb[nt][e];
                }
        }
        __syncthreads();                 // all warps done reading K
        #pragma unroll
        for (int nt=0; nt<4; nt++)
            #pragma unroll
            for (int e=0; e<4; e++) {
                int il = mi + g + ((e>=2)?8:0);
                int jl = nh + nt*8 + 2*t4 + (e&1);
                __nv_bfloat16 h, l;
                bsplit(S[nt][e], h, l);
                Ksh[il*ASTR+jl] = h; Ksl[il*ASTR+jl] = l;   // S into K buffer
            }
        __syncthreads();
        gemm3v(o, Ksh, Ksl, Vsh, Vsl, mi, nh, lane);
    }
    #pragma unroll
    for (int nt=0; nt<4; nt++)
        #pragma unroll
        for (int e=0; e<4; e++) {
            int il = mi + g + ((e>=2)?8:0);
            int jl = nh + nt*8 + 2*t4 + (e&1);
            g_yh[base + (size_t)(i0 + il)*K_ + jl] = o[nt][e];
        }
}

// ---------------- group-norm + scale/bias + gate (writes split yg) ----------
__global__ __launch_bounds__(512)
void ln_gate_kernel(const float* __restrict__ ln_w,
                    const float* __restrict__ ln_b) {
    int row = blockIdx.x;
    int b = row >> 10, t = row & (T_-1);
    int h = threadIdx.x >> 5;
    int lane = threadIdx.x & 31;
    size_t base = (((size_t)b*H_ + h)*T_ + t)*K_;
    float v0 = g_yh[base + lane*2];
    float v1 = g_yh[base + lane*2 + 1];
    float s = v0 + v1;
    #pragma unroll
    for (int off=16; off>0; off>>=1) s += __shfl_xor_sync(0xffffffffu, s, off);
    float mu = s * (1.f/64.f);
    float d0 = v0 - mu, d1 = v1 - mu;
    float sq = d0*d0 + d1*d1;
    #pragma unroll
    for (int off=16; off>0; off>>=1) sq += __shfl_xor_sync(0xffffffffu, sq, off);
    float inv = rsqrtf(sq*(1.f/64.f) + 6.4e-4f);
    int d = h*K_ + lane*2;
    size_t oo = (size_t)row*D_ + d;
    float y0 = ((d0*inv)*ln_w[d]   + ln_b[d])   * g_gt[oo];
    float y1 = ((d1*inv)*ln_w[d+1] + ln_b[d+1]) * g_gt[oo+1];
    __nv_bfloat16 hh, ll;
    bsplit(y0, hh, ll); g_ygh[oo]   = hh; g_ygl[oo]   = ll;
    bsplit(y1, hh, ll); g_ygh[oo+1] = hh; g_ygl[oo+1] = ll;
}

// ---------------- host launch ------------------------------------------------
extern "C" void kernel_launch(void* const* d_in, const int* in_sizes, int n_in,
                              void* d_out, int out_size) {
    const float* x        = (const float*)d_in[0];
    const float* maa_x    = (const float*)d_in[1];
    const float* maa_w    = (const float*)d_in[2];
    const float* maa_k    = (const float*)d_in[3];
    const float* maa_v    = (const float*)d_in[4];
    const float* maa_r    = (const float*)d_in[5];
    const float* maa_g    = (const float*)d_in[6];
    const float* maa_w1   = (const float*)d_in[7];   // (D, 160)
    const float* maa_w2   = (const float*)d_in[8];   // (5, 32, D)
    const float* tdecay   = (const float*)d_in[9];   // (1,1,D)
    const float* dec_w1   = (const float*)d_in[10];  // (D, 64)
    const float* dec_w2   = (const float*)d_in[11];  // (64, D)
    const float* W_r      = (const float*)d_in[12];
    const float* W_k      = (const float*)d_in[13];
    const float* W_v      = (const float*)d_in[14];
    const float* W_g      = (const float*)d_in[15];
    const float* W_o      = (const float*)d_in[16];
    const float* ln_w     = (const float*)d_in[17];
    const float* ln_b     = (const float*)d_in[18];
    float* out = (float*)d_out;

    float *p_xmix, *p_xxx, *p_xw, *p_r, *p_k, *p_v, *p_gt, *p_w, *p_wtmp;
    __nv_bfloat16 *p_xmh, *p_xml, *p_Wh, *p_Wl, *p_ygh, *p_ygl;
    cudaGetSymbolAddress((void**)&p_xmix, g_xmix);
    cudaGetSymbolAddress((void**)&p_xxx,  g_xxx);
    cudaGetSymbolAddress((void**)&p_xw,   g_xw);
    cudaGetSymbolAddress((void**)&p_r,    g_r);
    cudaGetSymbolAddress((void**)&p_k,    g_k);
    cudaGetSymbolAddress((void**)&p_v,    g_v);
    cudaGetSymbolAddress((void**)&p_gt,   g_gt);
    cudaGetSymbolAddress((void**)&p_w,    g_w);
    cudaGetSymbolAddress((void**)&p_wtmp, g_wtmp);
    cudaGetSymbolAddress((void**)&p_xmh,  g_xmh);
    cudaGetSymbolAddress((void**)&p_xml,  g_xml);
    cudaGetSymbolAddress((void**)&p_Wh,   g_Wh);
    cudaGetSymbolAddress((void**)&p_Wl,   g_Wl);
    cudaGetSymbolAddress((void**)&p_ygh,  g_ygh);
    cudaGetSymbolAddress((void**)&p_ygl,  g_ygl);

    // 1) dxprev + xmix
    prep_kernel<<<(BTD+255)/256, 256>>>(x, maa_x);

    // 2) split all 5 big weights (one kernel, vectorized)
    split5_kernel<<<(5*DD_/4 + 255)/256, 256>>>(W_r, W_k, W_v, W_g, W_o);

    // 3) xxx = tanh(xmix @ maa_w1)    (tf32)
    mma_gemm<EP_TANH><<<dim3(3,32), 256>>>(
        p_xmix, D_, maa_w1, 160, p_xxx, 160, BT_, 160, D_, nullptr);

    // 4) all 5 mixes, one f per grid.z; writes fp32 xw + split xk/xv/xr/xg
    mix_fused2<<<dim3(16,32,5), 256>>>(
        x, maa_w2, maa_w, maa_k, maa_v, maa_r, maa_g);

    // 5) all 4 projections in one batched launch (2-stage, 48 KB smem)
    {
        GemmBatch batch;
        batch.j[0] = { p_xmh + 2*(size_t)BTD, p_xml + 2*(size_t)BTD,
                       p_Wh + 0*(size_t)DD_,  p_Wl + 0*(size_t)DD_, p_r,  0 };
        batch.j[1] = { p_xmh + 0*(size_t)BTD, p_xml + 0*(size_t)BTD,
                       p_Wh + 1*(size_t)DD_,  p_Wl + 1*(size_t)DD_, p_k,  0 };
        batch.j[2] = { p_xmh + 1*(size_t)BTD, p_xml + 1*(size_t)BTD,
                       p_Wh + 2*(size_t)DD_,  p_Wl + 2*(size_t)DD_, p_v,  0 };
        batch.j[3] = { p_xmh + 3*(size_t)BTD, p_xml + 3*(size_t)BTD,
                       p_Wh + 3*(size_t)DD_,  p_Wl + 3*(size_t)DD_, p_gt, 1 };
        bgemm2<<<dim3(8,32,4), 256>>>(batch);
    }

    // 6) w = time_decay + tanh(xw @ dec_w1) @ dec_w2   (tf32 tensor cores)
    mma_gemm<EP_TANH><<<dim3(1,32), 256>>>(
        p_xw, D_, dec_w1, 64, p_wtmp, 64, BT_, 64, D_, nullptr);
    mma_gemm<EP_BIAS><<<dim3(16,32), 256>>>(
        p_wtmp, 64, dec_w2, D_, p_w, D_, BT_, D_, 64, tdecay);

    // 7) cumsum prefix (pass 1) + exp factors full-chip (pass 2)
    headprep_sums<<<B_*H_, 1024>>>();
    headprep2<<<dim3(B_*H_, 16), 256>>>();

    // 8) bidirectional attention (bf16x3, ldmatrix, 8 arrays -> 3 CTAs/SM)
    static const int ATTN_SMEM = 8*AARR*2;   // 73728 B
    cudaFuncSetAttribute(attn_bf16,
                         cudaFuncAttributeMaxDynamicSharedMemorySize, ATTN_SMEM);
    attn_bf16<<<dim3(B_*H_, 16), 256, ATTN_SMEM>>>();

    // 9) group-norm + gate (writes split yg)
    ln_gate_kernel<<<BT_, 512>>>(ln_w, ln_b);

    // 10) out = yg @ W_o^T (same batched kernel, single job)
    {
        GemmBatch batch;
        batch.j[0] = { p_ygh, p_ygl, p_Wh + 4*(size_t)DD_, p_Wl + 4*(size_t)DD_,
                       out, 0 };
        batch.j[1] = batch.j[0];
        batch.j[2] = batch.j[0];
        batch.j[3] = batch.j[0];
        bgemm2<<<dim3(8,32,1), 256>>>(batch);
    }
}